// round 10
// baseline (speedup 1.0000x reference)
#include <cuda_runtime.h>

// JointIntegralRegressor: soft-argmax over [16,24,64,64,64] fp32 heatmaps.
// SINGLE launch: 3072 producer CTAs + 384 combiner CTAs at the grid tail.
// R10: force R1's producer codegen back (launch_bounds minBlocks=6 -> 40-reg
// budget, higher LDG MLP) and quarantine the combiner in a __noinline__
// cold function so it can't perturb the producer's register schedule.

#define DIM_W 64
#define DIM_H 64
#define DIM_D 64
#define SLICES 384                           // 16*24
#define SLICE_ELEMS (DIM_D * DIM_H * DIM_W)  // 262144
#define CHUNKS_PER_SLICE 8
#define CHUNK_ELEMS (SLICE_ELEMS / CHUNKS_PER_SLICE)   // 32768
#define NCHUNKS (SLICES * CHUNKS_PER_SLICE)            // 3072
#define P1_THREADS 256
#define V4_PER_THREAD (CHUNK_ELEMS / 4 / P1_THREADS)   // 32

__device__ float4 g_partials[NCHUNKS];
__device__ unsigned int g_cnt[SLICES];       // zero-init; combiner self-resets

// Cold path: one active warp combines a slice's 8 partials.
__device__ __noinline__ void combine_slice(int slice, int tid,
                                           float* __restrict__ out) {
    if (tid >= 32) return;
    const int lane = tid;

    if (lane == 0) {
        unsigned int c;
        for (;;) {
            asm volatile("ld.acquire.gpu.global.u32 %0, [%1];"
                         : "=r"(c) : "l"(&g_cnt[slice]) : "memory");
            if (c >= CHUNKS_PER_SLICE) break;
            __nanosleep(64);
        }
    }
    __syncwarp();

    float s = 0.f, sx = 0.f, sy = 0.f, sz = 0.f;
    if (lane < CHUNKS_PER_SLICE) {
        float px, py, pz, pw;
        asm volatile("ld.global.cg.v4.f32 {%0, %1, %2, %3}, [%4];"
                     : "=f"(px), "=f"(py), "=f"(pz), "=f"(pw)
                     : "l"(&g_partials[slice * CHUNKS_PER_SLICE + lane])
                     : "memory");
        s = px; sx = py; sy = pz; sz = pw;
    }

    #pragma unroll
    for (int off = 4; off > 0; off >>= 1) {
        s  += __shfl_down_sync(0xFFFFFFFFu, s,  off);
        sx += __shfl_down_sync(0xFFFFFFFFu, sx, off);
        sy += __shfl_down_sync(0xFFFFFFFFu, sy, off);
        sz += __shfl_down_sync(0xFFFFFFFFu, sz, off);
    }

    if (lane == 0) {
        const float inv = 1.0f / s;
        const float scale = 1.0f / 64.0f;
        out[slice * 3 + 0] = sx * inv * scale - 0.5f;
        out[slice * 3 + 1] = sy * inv * scale - 0.5f;
        out[slice * 3 + 2] = sz * inv * scale - 0.5f;
        // Reset for next graph replay (same L2 path as the red target).
        asm volatile("st.global.cg.u32 [%0], %1;"
                     :: "l"(&g_cnt[slice]), "r"(0u) : "memory");
    }
}

__global__ __launch_bounds__(P1_THREADS, 6)   // 6 CTAs/SM -> 40-reg budget (R1 codegen)
void jir_single(const float* __restrict__ in, float* __restrict__ out) {
    const int bid = blockIdx.x;
    const int tid = threadIdx.x;

    if (bid >= NCHUNKS) {
        combine_slice(bid - NCHUNKS, tid, out);
        return;
    }

    // ---------------- producer (bit-identical best-known mainloop) ----------
    const int chunk = bid;
    const int slice = chunk >> 3;

    const float4* __restrict__ in4 =
        reinterpret_cast<const float4*>(in) + (long long)chunk * (CHUNK_ELEMS / 4);
    const int elem0 = (chunk & (CHUNKS_PER_SLICE - 1)) * CHUNK_ELEMS;

    float s = 0.f, sx = 0.f, sy = 0.f, sz = 0.f;

    #pragma unroll 4
    for (int it = 0; it < V4_PER_THREAD; ++it) {
        const int idx4 = it * P1_THREADS + tid;
        const float4 v = __ldcs(&in4[idx4]);        // read-once: evict-first

        const int e  = elem0 + idx4 * 4;
        const float w0 = (float)(e & (DIM_W - 1));
        const int   hd = e >> 6;
        const float hf = (float)(hd & (DIM_H - 1));
        const float df = (float)(hd >> 6);

        const float e0 = __expf(v.x);
        const float e1 = __expf(v.y);
        const float e2 = __expf(v.z);
        const float e3 = __expf(v.w);

        const float sp = (e0 + e1) + (e2 + e3);
        float inner = fmaf(2.f, e2, e1);
        inner       = fmaf(3.f, e3, inner);

        s  += sp;
        sx += fmaf(w0, sp, inner);
        sy  = fmaf(hf, sp, sy);
        sz  = fmaf(df, sp, sz);
    }

    #pragma unroll
    for (int off = 16; off > 0; off >>= 1) {
        s  += __shfl_down_sync(0xFFFFFFFFu, s,  off);
        sx += __shfl_down_sync(0xFFFFFFFFu, sx, off);
        sy += __shfl_down_sync(0xFFFFFFFFu, sy, off);
        sz += __shfl_down_sync(0xFFFFFFFFu, sz, off);
    }

    __shared__ float4 red[P1_THREADS / 32];
    const int warp = tid >> 5;
    const int lane = tid & 31;
    if (lane == 0) red[warp] = make_float4(s, sx, sy, sz);
    __syncthreads();

    if (tid == 0) {
        float4 acc = red[0];
        #pragma unroll
        for (int i = 1; i < P1_THREADS / 32; ++i) {
            acc.x += red[i].x;
            acc.y += red[i].y;
            acc.z += red[i].z;
            acc.w += red[i].w;
        }
        // Publish partial (L2), then fire-and-forget release bump.
        asm volatile("st.global.cg.v4.f32 [%0], {%1, %2, %3, %4};"
                     :: "l"(&g_partials[chunk]),
                        "f"(acc.x), "f"(acc.y), "f"(acc.z), "f"(acc.w)
                     : "memory");
        asm volatile("red.release.gpu.global.add.u32 [%0], %1;"
                     :: "l"(&g_cnt[slice]), "r"(1u) : "memory");
    }
}

extern "C" void kernel_launch(void* const* d_in, const int* in_sizes, int n_in,
                              void* d_out, int out_size) {
    const float* heatmaps = (const float*)d_in[0];
    float* out = (float*)d_out;
    jir_single<<<NCHUNKS + SLICES, P1_THREADS>>>(heatmaps, out);
}

// round 11
// speedup vs baseline: 1.0147x; 1.0147x over previous
#include <cuda_runtime.h>

// JointIntegralRegressor: soft-argmax over [16,24,64,64,64] fp32 heatmaps.
// Two kernels (structure of best-known 64.0us config). R11: pass1 mainloop
// restructured into explicit 8-deep front-batched load batches (MLP_p1=8
// per warp) with a 64-reg budget (launch_bounds minBlocks=4) to push the
// streaming read bandwidth past 6.8 TB/s.

#define DIM_W 64
#define DIM_H 64
#define DIM_D 64
#define SLICES 384                           // 16*24
#define SLICE_ELEMS (DIM_D * DIM_H * DIM_W)  // 262144
#define CHUNKS_PER_SLICE 8
#define CHUNK_ELEMS (SLICE_ELEMS / CHUNKS_PER_SLICE)   // 32768
#define NCHUNKS (SLICES * CHUNKS_PER_SLICE)            // 3072
#define P1_THREADS 256
#define V4_PER_THREAD (CHUNK_ELEMS / 4 / P1_THREADS)   // 32
#define BATCH 8
#define NBATCH (V4_PER_THREAD / BATCH)                 // 4

// Scratch for per-chunk partial moments: (s, sx, sy, sz).
__device__ float4 g_partials[NCHUNKS];

__global__ __launch_bounds__(P1_THREADS, 4)   // 64-reg budget: room for 8 batched float4
void jir_pass1(const float* __restrict__ in) {
    const int chunk = blockIdx.x;
    const int tid = threadIdx.x;

    const float4* __restrict__ in4 =
        reinterpret_cast<const float4*>(in) + (long long)chunk * (CHUNK_ELEMS / 4);
    const int elem0 = (chunk & (CHUNKS_PER_SLICE - 1)) * CHUNK_ELEMS;

    float s = 0.f, sx = 0.f, sy = 0.f, sz = 0.f;

    for (int b = 0; b < NBATCH; ++b) {
        // Front-batched loads: 8 consecutive LDG.128 with no consumer between.
        float4 v[BATCH];
        #pragma unroll
        for (int j = 0; j < BATCH; ++j) {
            v[j] = __ldcs(&in4[(b * BATCH + j) * P1_THREADS + tid]);
        }

        #pragma unroll
        for (int j = 0; j < BATCH; ++j) {
            const int idx4 = (b * BATCH + j) * P1_THREADS + tid;
            const int e  = elem0 + idx4 * 4;
            const float w0 = (float)(e & (DIM_W - 1));
            const int   hd = e >> 6;
            const float hf = (float)(hd & (DIM_H - 1));
            const float df = (float)(hd >> 6);

            const float e0 = __expf(v[j].x);
            const float e1 = __expf(v[j].y);
            const float e2 = __expf(v[j].z);
            const float e3 = __expf(v[j].w);

            const float sp = (e0 + e1) + (e2 + e3);
            // sum_k e_k * (w0 + k) = w0*sp + (e1 + 2*e2 + 3*e3)
            float inner = fmaf(2.f, e2, e1);
            inner       = fmaf(3.f, e3, inner);

            s  += sp;
            sx += fmaf(w0, sp, inner);
            sy  = fmaf(hf, sp, sy);
            sz  = fmaf(df, sp, sz);
        }
    }

    // Block reduction: warp shuffle, then warp-partials through shared memory.
    #pragma unroll
    for (int off = 16; off > 0; off >>= 1) {
        s  += __shfl_down_sync(0xFFFFFFFFu, s,  off);
        sx += __shfl_down_sync(0xFFFFFFFFu, sx, off);
        sy += __shfl_down_sync(0xFFFFFFFFu, sy, off);
        sz += __shfl_down_sync(0xFFFFFFFFu, sz, off);
    }

    __shared__ float4 red[P1_THREADS / 32];
    const int warp = tid >> 5;
    const int lane = tid & 31;
    if (lane == 0) red[warp] = make_float4(s, sx, sy, sz);
    __syncthreads();

    if (tid == 0) {
        float4 acc = red[0];
        #pragma unroll
        for (int i = 1; i < P1_THREADS / 32; ++i) {
            acc.x += red[i].x;
            acc.y += red[i].y;
            acc.z += red[i].z;
            acc.w += red[i].w;
        }
        g_partials[chunk] = acc;
    }
}

// One 32-thread block per slice: lanes 0..7 load one partial each, reduce.
__global__ __launch_bounds__(32)
void jir_pass2(float* __restrict__ out) {
    const int slice = blockIdx.x;
    const int lane = threadIdx.x;

    float s = 0.f, sx = 0.f, sy = 0.f, sz = 0.f;
    if (lane < CHUNKS_PER_SLICE) {
        const float4 p = g_partials[slice * CHUNKS_PER_SLICE + lane];
        s = p.x; sx = p.y; sy = p.z; sz = p.w;
    }

    #pragma unroll
    for (int off = 4; off > 0; off >>= 1) {
        s  += __shfl_down_sync(0xFFFFFFFFu, s,  off);
        sx += __shfl_down_sync(0xFFFFFFFFu, sx, off);
        sy += __shfl_down_sync(0xFFFFFFFFu, sy, off);
        sz += __shfl_down_sync(0xFFFFFFFFu, sz, off);
    }

    if (lane == 0) {
        const float inv = 1.0f / s;
        const float scale = 1.0f / 64.0f;
        out[slice * 3 + 0] = sx * inv * scale - 0.5f;
        out[slice * 3 + 1] = sy * inv * scale - 0.5f;
        out[slice * 3 + 2] = sz * inv * scale - 0.5f;
    }
}

extern "C" void kernel_launch(void* const* d_in, const int* in_sizes, int n_in,
                              void* d_out, int out_size) {
    const float* heatmaps = (const float*)d_in[0];
    float* out = (float*)d_out;

    jir_pass1<<<NCHUNKS, P1_THREADS>>>(heatmaps);
    jir_pass2<<<SLICES, 32>>>(out);
}